// round 15
// baseline (speedup 1.0000x reference)
#include <cuda_runtime.h>
#include <cuda_fp16.h>
#include <cstdint>

#define S 2048
#define HID 2048
#define NH 16
#define HD 128
#define BATCH 2
#define MROWS (BATCH*S)   // 4096

typedef unsigned long long ull;

// ---------------- scratch (static device allocations; no cudaMalloc) --------
__device__ float  g_V [(size_t)MROWS*HID];
__device__ __half g_Sh[(size_t)BATCH*NH*S*S];  // raw scaled scores, fp16 (268 MB)
__device__ float  g_m [BATCH*NH*S];
__device__ float  g_li[BATCH*NH*S];
__device__ float  g_pm[(size_t)BATCH*NH*S*16];
__device__ float  g_pl[(size_t)BATCH*NH*S*16];

__device__ __half g_fA [(size_t)MROWS*HID];
__device__ __half g_fW [(size_t)HID*HID];
__device__ __half g_fQ [(size_t)MROWS*HID];
__device__ __half g_fK [(size_t)MROWS*HID];
__device__ __half g_fVt[(size_t)HID*MROWS];

// ======================= PTX helpers =========================================
__device__ __forceinline__ uint32_t smem_u32(const void* p){
    uint32_t a;
    asm("{ .reg .u64 t; cvta.to.shared.u64 t, %1; cvt.u32.u64 %0, t; }" : "=r"(a) : "l"(p));
    return a;
}
#define CP16(sm, gp)  asm volatile("cp.async.cg.shared.global [%0], [%1], 16;" :: "r"(sm), "l"(gp) : "memory")
#define CP_COMMIT()   asm volatile("cp.async.commit_group;" ::: "memory")
#define CP_WAIT2()    asm volatile("cp.async.wait_group 2;" ::: "memory")
#define CP_WAIT1()    asm volatile("cp.async.wait_group 1;" ::: "memory")
#define CP_WAIT0()    asm volatile("cp.async.wait_group 0;" ::: "memory")

#define LDSM4(R, A) asm volatile("ldmatrix.sync.aligned.m8n8.x4.shared.b16 {%0,%1,%2,%3}, [%4];" \
    : "=r"((R)[0]), "=r"((R)[1]), "=r"((R)[2]), "=r"((R)[3]) : "r"(A))

#define MMAF16(D, Af, B0, B1) asm volatile( \
    "mma.sync.aligned.m16n8k16.row.col.f32.f16.f16.f32 " \
    "{%0,%1,%2,%3}, {%4,%5,%6,%7}, {%8,%9}, {%0,%1,%2,%3};" \
    : "+f"((D)[0]), "+f"((D)[1]), "+f"((D)[2]), "+f"((D)[3]) \
    : "r"((Af)[0]), "r"((Af)[1]), "r"((Af)[2]), "r"((Af)[3]), \
      "r"(B0), "r"(B1))

__device__ __forceinline__ uint32_t h2u(float a, float b){
    __half2 h = __floats2half2_rn(a, b);
    return *(uint32_t*)&h;
}

// tail-aware wait: #outstanding-after-k = min(k+2, last) - k
#define PIPE_WAIT(k, last) do { \
    if ((k) < (last) - 1) { CP_WAIT2(); } \
    else if ((k) == (last) - 1) { CP_WAIT1(); } \
    else { CP_WAIT0(); } } while (0)

// ======================= prep kernels ========================================
__global__ void __launch_bounds__(256) cvt_f16(
    const float* __restrict__ in, __half* __restrict__ out, int n4)
{
    int i = blockIdx.x * 256 + threadIdx.x;
    if (i >= n4) return;
    float4 v = ((const float4*)in)[i];
    uint32_t a = h2u(v.x, v.y), b = h2u(v.z, v.w);
    ((uint2*)out)[i] = make_uint2(a, b);
}

__global__ void __launch_bounds__(256) transpose_f16(
    const float* __restrict__ in, __half* __restrict__ out, int CI, int RI)
{
    __shared__ float ts[32][33];
    int tx = threadIdx.x, ty = threadIdx.y;
    int n0 = blockIdx.x * 32, k0 = blockIdx.y * 32;
#pragma unroll
    for (int j = 0; j < 4; j++)
        ts[ty + j * 8][tx] = in[(size_t)(k0 + ty + j * 8) * CI + n0 + tx];
    __syncthreads();
#pragma unroll
    for (int j = 0; j < 4; j++)
        out[(size_t)(n0 + ty + j * 8) * RI + k0 + tx] = __float2half(ts[tx][ty + j * 8]);
}

// ======================= fp16 HMMA GEMM: C = A@W + bias ======================
#define BK 32
#define NKCH (HID/BK)                 // 64
#define SSTR 40
#define MATB (128*SSTR*2)             // 10240 B
#define STG2 (2*MATB)                 // 20480 B per stage (A+B)
#define GSM4 (4*STG2)                 // 81920 B
#define AVS  (GSM4 + 1024)

__global__ void __launch_bounds__(256) gemm_f16(
    const __half* __restrict__ A, const __half* __restrict__ B,
    const float* __restrict__ bias, float* __restrict__ C,
    __half* __restrict__ Cf)
{
    extern __shared__ __align__(128) char smg[];
    uint32_t sb = smem_u32(smg);
    int tid = threadIdx.x, lane = tid & 31, wid = tid >> 5;
    int brow = blockIdx.y * 128, bcol = blockIdx.x * 128;
    int wm = (wid >> 1) * 32, wn = (wid & 1) * 64;

    int lr = tid >> 2, lc = (tid & 3) * 8;
    const __half* srcA0 = A + (size_t)(brow + lr) * HID + lc;
    const __half* srcA1 = A + (size_t)(brow + lr + 64) * HID + lc;
    const __half* srcB0 = B + (size_t)(bcol + lr) * HID + lc;
    const __half* srcB1 = B + (size_t)(bcol + lr + 64) * HID + lc;
    uint32_t d0 = (uint32_t)(lr * SSTR + lc) * 2;
    uint32_t d1 = (uint32_t)((lr + 64) * SSTR + lc) * 2;

#define LOAD_CHUNK(kk, st) do { \
    uint32_t bb = sb + (uint32_t)(st) * STG2; \
    int k0 = (kk) * BK; \
    CP16(bb + d0, srcA0 + k0); CP16(bb + d1, srcA1 + k0); \
    CP16(bb + MATB + d0, srcB0 + k0); CP16(bb + MATB + d1, srcB1 + k0); \
    CP_COMMIT(); } while (0)

    uint32_t a_off  = (uint32_t)((wm + (lane & 15)) * SSTR + ((lane >> 1) & 8)) * 2;
    uint32_t b4_off = (uint32_t)((wn + (lane & 7) + ((lane >> 4) << 3)) * SSTR + (lane & 8)) * 2;

    float acc[2][8][4];
#pragma unroll
    for (int mt = 0; mt < 2; mt++)
#pragma unroll
        for (int nt = 0; nt < 8; nt++)
#pragma unroll
            for (int j = 0; j < 4; j++) acc[mt][nt][j] = 0.0f;

    LOAD_CHUNK(0, 0);
    LOAD_CHUNK(1, 1);
    LOAD_CHUNK(2, 2);

    for (int k = 0; k < NKCH; k++) {
        PIPE_WAIT(k, NKCH - 1);
        __syncthreads();
        if (k + 3 < NKCH) LOAD_CHUNK(k + 3, (k + 3) & 3);
        uint32_t stb = sb + (uint32_t)(k & 3) * STG2;
#pragma unroll
        for (int kst = 0; kst < 2; kst++) {
            uint32_t kb = (uint32_t)kst * 32;
            uint32_t a[2][4], b4[4][4];
            LDSM4(a[0], stb + a_off + kb);
            LDSM4(a[1], stb + a_off + kb + 16*SSTR*2);
#pragma unroll
            for (int g = 0; g < 4; g++)
                LDSM4(b4[g], stb + MATB + b4_off + kb + g*16*SSTR*2);
#pragma unroll
            for (int mt = 0; mt < 2; mt++)
#pragma unroll
                for (int g = 0; g < 4; g++) {
                    MMAF16(acc[mt][2*g],   a[mt], b4[g][0], b4[g][1]);
                    MMAF16(acc[mt][2*g+1], a[mt], b4[g][2], b4[g][3]);
                }
        }
    }
#undef LOAD_CHUNK

    int gid = lane >> 2, tig = lane & 3;
#pragma unroll
    for (int mt = 0; mt < 2; mt++) {
        int m0 = brow + wm + mt * 16 + gid;
#pragma unroll
        for (int nt = 0; nt < 8; nt++) {
            int n0 = bcol + wn + nt * 8 + tig * 2;
            float2 bb = *(const float2*)(bias + n0);
            float v0 = acc[mt][nt][0] + bb.x, v1 = acc[mt][nt][1] + bb.y;
            float v2 = acc[mt][nt][2] + bb.x, v3 = acc[mt][nt][3] + bb.y;
            if (Cf) {
                *(uint32_t*)(Cf + (size_t)m0 * HID + n0)     = h2u(v0, v1);
                *(uint32_t*)(Cf + (size_t)(m0+8) * HID + n0) = h2u(v2, v3);
            } else {
                *(float2*)(C + (size_t)m0 * HID + n0)     = make_float2(v0, v1);
                *(float2*)(C + (size_t)(m0+8) * HID + n0) = make_float2(v2, v3);
            }
        }
    }
}

// ================ attention scores: S = scale * Q @ K^T (fp16 HMMA) =========
#define SNK (HD/BK)   // 4
__global__ void __launch_bounds__(256) attn_scores_mma()
{
    extern __shared__ __align__(128) char smg[];
    uint32_t sb = smem_u32(smg);
    int tid = threadIdx.x, lane = tid & 31, wid = tid >> 5;
    int kt = blockIdx.x, qt = blockIdx.y, bh = blockIdx.z;
    int b = bh >> 4, h = bh & 15;
    int wm = (wid >> 1) * 32, wn = (wid & 1) * 64;

    int lr = tid >> 2, lc = (tid & 3) * 8;
    const __half* srcA0 = g_fQ + (size_t)(b*S + qt*128 + lr) * HID + h*HD + lc;
    const __half* srcA1 = srcA0 + (size_t)64 * HID;
    const __half* srcB0 = g_fK + (size_t)(b*S + kt*128 + lr) * HID + h*HD + lc;
    const __half* srcB1 = srcB0 + (size_t)64 * HID;
    uint32_t d0 = (uint32_t)(lr * SSTR + lc) * 2;
    uint32_t d1 = (uint32_t)((lr + 64) * SSTR + lc) * 2;

#define LOAD_CHUNK(kk, st) do { \
    uint32_t bb = sb + (uint32_t)(st) * STG2; \
    int k0 = (kk) * BK; \
    CP16(bb + d0, srcA0 + k0); CP16(bb + d1, srcA1 + k0); \
    CP16(bb + MATB + d0, srcB0 + k0); CP16(bb + MATB + d1, srcB1 + k0); \
    CP_COMMIT(); } while (0)

    uint32_t a_off  = (uint32_t)((wm + (lane & 15)) * SSTR + ((lane >> 1) & 8)) * 2;
    uint32_t b4_off = (uint32_t)((wn + (lane & 7) + ((lane >> 4) << 3)) * SSTR + (lane & 8)) * 2;

    float acc[2][8][4];
#pragma unroll
    for (int mt = 0; mt < 2; mt++)
#pragma unroll
        for (int nt = 0; nt < 8; nt++)
#pragma unroll
            for (int j = 0; j < 4; j++) acc[mt][nt][j] = 0.0f;

    LOAD_CHUNK(0, 0);
    LOAD_CHUNK(1, 1);
    LOAD_CHUNK(2, 2);

    for (int k = 0; k < SNK; k++) {
        PIPE_WAIT(k, SNK - 1);
        __syncthreads();
        if (k + 3 < SNK) LOAD_CHUNK(k + 3, (k + 3) & 3);
        uint32_t stb = sb + (uint32_t)(k & 3) * STG2;
#pragma unroll
        for (int kst = 0; kst < 2; kst++) {
            uint32_t kb = (uint32_t)kst * 32;
            uint32_t a[2][4], b4[4][4];
            LDSM4(a[0], stb + a_off + kb);
            LDSM4(a[1], stb + a_off + kb + 16*SSTR*2);
#pragma unroll
            for (int g = 0; g < 4; g++)
                LDSM4(b4[g], stb + MATB + b4_off + kb + g*16*SSTR*2);
#pragma unroll
            for (int mt = 0; mt < 2; mt++)
#pragma unroll
                for (int g = 0; g < 4; g++) {
                    MMAF16(acc[mt][2*g],   a[mt], b4[g][0], b4[g][1]);
                    MMAF16(acc[mt][2*g+1], a[mt], b4[g][2], b4[g][3]);
                }
        }
    }
#undef LOAD_CHUNK

    const float scale = 0.08838834764831843f;   // 1/sqrt(128)
#pragma unroll
    for (int mt = 0; mt < 2; mt++)
#pragma unroll
        for (int nt = 0; nt < 8; nt++)
#pragma unroll
            for (int j = 0; j < 4; j++) acc[mt][nt][j] *= scale;

    int gid = lane >> 2, tig = lane & 3;
    size_t srow0 = (size_t)bh * S + (size_t)qt * 128;
#pragma unroll
    for (int mt = 0; mt < 2; mt++) {
        size_t m0 = srow0 + wm + mt * 16 + gid;
#pragma unroll
        for (int nt = 0; nt < 8; nt++) {
            int n0 = kt * 128 + wn + nt * 8 + tig * 2;
            *(uint32_t*)&g_Sh[m0 * S + n0]       = h2u(acc[mt][nt][0], acc[mt][nt][1]);
            *(uint32_t*)&g_Sh[(m0 + 8) * S + n0] = h2u(acc[mt][nt][2], acc[mt][nt][3]);
        }
    }

    __syncthreads();
    float* sm = (float*)smg;          // [2][128]
    float* sl = sm + 256;             // [2][128]
#pragma unroll
    for (int mt = 0; mt < 2; mt++) {
#pragma unroll
        for (int half = 0; half < 2; half++) {
            float mx = -1e30f;
#pragma unroll
            for (int nt = 0; nt < 8; nt++)
                mx = fmaxf(mx, fmaxf(acc[mt][nt][half*2], acc[mt][nt][half*2+1]));
            mx = fmaxf(mx, __shfl_xor_sync(0xffffffffu, mx, 1));
            mx = fmaxf(mx, __shfl_xor_sync(0xffffffffu, mx, 2));
            float se = 0.0f;
#pragma unroll
            for (int nt = 0; nt < 8; nt++)
                se += __expf(acc[mt][nt][half*2] - mx) + __expf(acc[mt][nt][half*2+1] - mx);
            se += __shfl_xor_sync(0xffffffffu, se, 1);
            se += __shfl_xor_sync(0xffffffffu, se, 2);
            if (tig == 0) {
                int r = wm + mt * 16 + half * 8 + gid;
                sm[(wid & 1) * 128 + r] = mx;
                sl[(wid & 1) * 128 + r] = se;
            }
        }
    }
    __syncthreads();
    if (tid < 128) {
        float m0 = sm[tid], m1 = sm[128 + tid];
        float l0 = sl[tid], l1 = sl[128 + tid];
        float M = fmaxf(m0, m1);
        float L = l0 * __expf(m0 - M) + l1 * __expf(m1 - M);
        size_t q = (size_t)bh * S + (size_t)qt * 128 + tid;
        g_pm[q * 16 + kt] = M;
        g_pl[q * 16 + kt] = L;
    }
}

// ================ combine partial stats -> m, 1/l ============================
__global__ void __launch_bounds__(256) combine_stats()
{
    int r = blockIdx.x * 256 + threadIdx.x;
    float M = -1e30f;
#pragma unroll
    for (int i = 0; i < 16; i++) M = fmaxf(M, g_pm[(size_t)r * 16 + i]);
    float L = 0.0f;
#pragma unroll
    for (int i = 0; i < 16; i++)
        L += g_pl[(size_t)r * 16 + i] * __expf(g_pm[(size_t)r * 16 + i] - M);
    g_m[r]  = M;
    g_li[r] = 1.0f / L;
}

// ================ attn AV: attended = softmax(S) @ V (fp16 HMMA) =============
// Single-barrier 4-stage pipeline; P converted one chunk ahead.
__global__ void __launch_bounds__(256) attn_av_mma()
{
    extern __shared__ __align__(128) char smg[];
    uint32_t sb = smem_u32(smg);
    float* msh = (float*)(smg + GSM4);         // [128]
    float* lih = msh + 128;                    // [128]
    int tid = threadIdx.x, lane = tid & 31, wid = tid >> 5;
    int qt = blockIdx.x, b = blockIdx.y, h = blockIdx.z;
    int bh = b * NH + h;
    int wm = (wid >> 1) * 32, wn = (wid & 1) * 64;

    if (tid < 128) {
        size_t q = (size_t)bh * S + (size_t)qt * 128 + tid;
        msh[tid] = g_m[q];
        lih[tid] = g_li[q];
    }
    __syncthreads();

    int pr = tid >> 1, pc = (tid & 1) * 16;
    const __half* srcP = g_Sh + ((size_t)bh * S + (size_t)qt * 128 + pr) * S + pc;
    float pm_r = msh[pr], pli_r = lih[pr];
    uint32_t pdst = (uint32_t)(pr * SSTR + pc) * 2;

    int lr = tid >> 2, lc = (tid & 3) * 8;
    const __half* srcV0 = g_fVt + (size_t)(h*HD + lr) * MROWS + b*S + lc;
    const __half* srcV1 = srcV0 + (size_t)64 * MROWS;
    uint32_t d0 = (uint32_t)(lr * SSTR + lc) * 2;
    uint32_t d1 = (uint32_t)((lr + 64) * SSTR + lc) * 2;

#define LOADV(kk, st) do { \
    uint32_t bb = sb + (uint32_t)(st) * STG2; \
    int k0 = (kk) * BK; \
    CP16(bb + MATB + d0, srcV0 + k0); CP16(bb + MATB + d1, srcV1 + k0); \
    CP_COMMIT(); } while (0)

#define CONVP(kk, st) do { \
    uint32_t bb = sb + (uint32_t)(st) * STG2; \
    int k0 = (kk) * BK; \
    _Pragma("unroll") \
    for (int j = 0; j < 2; j++) { \
        uint4 u = *(const uint4*)(srcP + k0 + j * 8); \
        float2 f0 = __half22float2(*(__half2*)&u.x); \
        float2 f1 = __half22float2(*(__half2*)&u.y); \
        float2 f2 = __half22float2(*(__half2*)&u.z); \
        float2 f3 = __half22float2(*(__half2*)&u.w); \
        uint32_t o0 = h2u(__expf(f0.x - pm_r) * pli_r, __expf(f0.y - pm_r) * pli_r); \
        uint32_t o1 = h2u(__expf(f1.x - pm_r) * pli_r, __expf(f1.y - pm_r) * pli_r); \
        uint32_t o2 = h2u(__expf(f2.x - pm_r) * pli_r, __expf(f2.y - pm_r) * pli_r); \
        uint32_t o3 = h2u(__expf(f3.x - pm_r) * pli_r, __expf(f3.y - pm_r) * pli_r); \
        asm volatile("st.shared.v4.b32 [%0], {%1, %2, %3, %4};" \
            :: "r"(bb + pdst + (uint32_t)j * 16), "r"(o0), "r"(o1), "r"(o2), "r"(o3)); \
    } } while (0)

    uint32_t a_off  = (uint32_t)((wm + (lane & 15)) * SSTR + ((lane >> 1) & 8)) * 2;
    uint32_t b4_off = (uint32_t)((wn + (lane & 7) + ((lane >> 4) << 3)) * SSTR + (lane & 8)) * 2;

    float acc[2][8][4];
#pragma unroll
    for (int mt = 0; mt < 2; mt++)
#pragma unroll
        for (int nt = 0; nt < 8; nt++)
#pragma unroll
            for (int j = 0; j < 4; j++) acc[mt][nt][j] = 0.0f;

    CONVP(0, 0);                       // P(0) into stage 0 (visible at iter-0 sync)
    LOADV(0, 0);
    LOADV(1, 1);
    LOADV(2, 2);

    for (int k = 0; k < NKCH; k++) {
        PIPE_WAIT(k, NKCH - 1);
        __syncthreads();               // V(k) + P(k) now visible; all warps past compute k-1
        if (k + 3 < NKCH) LOADV(k + 3, (k + 3) & 3);
        if (k + 1 < NKCH) CONVP(k + 1, (k + 1) & 3);   // stage (k+1)%4 last computed at k-3: free
        uint32_t stb = sb + (uint32_t)(k & 3) * STG2;
#pragma unroll
        for (int kst = 0; kst < 2; kst++) {
            uint32_t kb = (uint32_t)kst * 32;
            uint32_t a[2][4], b4[4][4];
            LDSM4(a[0], stb + a_off + kb);
            LDSM4(a[1], stb + a_off + kb + 16*SSTR*2);
#pragma unroll
            for (int g = 0; g < 4; g++)
                LDSM4(b4[g], stb + MATB + b4_off + kb + g*16*SSTR*2);
#pragma unroll
            for (int mt = 0; mt < 2; mt++)
#pragma unroll
                for (int g = 0; g < 4; g++) {
                    MMAF16(acc[mt][2*g],   a[mt], b4[g][0], b4[g][1]);
                    MMAF16(acc[mt][2*g+1], a[mt], b4[g][2], b4[g][3]);
                }
        }
    }
#undef LOADV
#undef CONVP

    int gid = lane >> 2, tig = lane & 3;
#pragma unroll
    for (int mt = 0; mt < 2; mt++) {
        size_t m0 = (size_t)(b * S + qt * 128 + wm + mt * 16 + gid);
#pragma unroll
        for (int nt = 0; nt < 8; nt++) {
            int n0 = h * HD + wn + nt * 8 + tig * 2;
            *(uint32_t*)(g_fA + m0 * HID + n0) =
                h2u(acc[mt][nt][0], acc[mt][nt][1]);
            *(uint32_t*)(g_fA + (m0+8) * HID + n0) =
                h2u(acc[mt][nt][2], acc[mt][nt][3]);
        }
    }
}

// ---------------- head-mean of attention weights (fp16 scores -> exp) -------
__global__ void __launch_bounds__(256) mean_attn(float* __restrict__ out2)
{
    int f = blockIdx.x * 256 + threadIdx.x;
    int b  = f >> 20;
    int r  = f & 1048575;
    int q  = r >> 9;
    int k4 = (r & 511) * 4;
    float mm[NH], ll[NH];
#pragma unroll
    for (int h = 0; h < NH; h++) {
        int bh = b * NH + h;
        mm[h] = g_m[bh * S + q];
        ll[h] = g_li[bh * S + q];
    }
    float4 acc = make_float4(0.f, 0.f, 0.f, 0.f);
#pragma unroll
    for (int h = 0; h < NH; h++) {
        size_t base = ((size_t)(b * NH + h) * S + q) * S + k4;
        uint2 u = *(const uint2*)&g_Sh[base];
        float2 f0 = __half22float2(*(__half2*)&u.x);
        float2 f1 = __half22float2(*(__half2*)&u.y);
        acc.x += __expf(f0.x - mm[h]) * ll[h];
        acc.y += __expf(f0.y - mm[h]) * ll[h];
        acc.z += __expf(f1.x - mm[h]) * ll[h];
        acc.w += __expf(f1.y - mm[h]) * ll[h];
    }
    const float inv = 1.0f / 16.0f;
    acc.x *= inv; acc.y *= inv; acc.z *= inv; acc.w *= inv;
    *(float4*)&out2[(size_t)f * 4] = acc;
}

// ---------------- launch ----------------------------------------------------
extern "C" void kernel_launch(void* const* d_in, const int* in_sizes, int n_in,
                              void* d_out, int out_size)
{
    const float* query = (const float*)d_in[0];
    const float* key   = (const float*)d_in[1];
    const float* value = (const float*)d_in[2];
    // d_in[3] rewards, d_in[4] mask: mathematically no-ops
    const float* Wq = (const float*)d_in[5];
    const float* bq = (const float*)d_in[6];
    const float* Wk = (const float*)d_in[7];
    const float* bk = (const float*)d_in[8];
    const float* Wv = (const float*)d_in[9];
    const float* bv = (const float*)d_in[10];
    const float* Wo = (const float*)d_in[11];
    const float* bo = (const float*)d_in[12];
    float* out = (float*)d_out;

    float *pV;
    cudaGetSymbolAddress((void**)&pV, g_V);
    __half *fA, *fW, *fQ, *fK, *fVt;
    cudaGetSymbolAddress((void**)&fA, g_fA);
    cudaGetSymbolAddress((void**)&fW, g_fW);
    cudaGetSymbolAddress((void**)&fQ, g_fQ);
    cudaGetSymbolAddress((void**)&fK, g_fK);
    cudaGetSymbolAddress((void**)&fVt, g_fVt);

    cudaFuncSetAttribute(gemm_f16,        cudaFuncAttributeMaxDynamicSharedMemorySize, GSM4);
    cudaFuncSetAttribute(attn_scores_mma, cudaFuncAttributeMaxDynamicSharedMemorySize, GSM4);
    cudaFuncSetAttribute(attn_av_mma,     cudaFuncAttributeMaxDynamicSharedMemorySize, AVS);

    const int NA4 = MROWS * HID / 4;
    dim3 tw(HID / 32, HID / 32), tb(32, 8);
    dim3 gg(HID / 128, MROWS / 128);   // (16, 32)

    // Q projection -> fp16
    cvt_f16<<<NA4 / 256, 256>>>(query, fA, NA4);
    transpose_f16<<<tw, tb>>>(Wq, fW, HID, HID);
    gemm_f16<<<gg, 256, GSM4>>>(fA, fW, bq, nullptr, fQ);
    // K projection -> fp16
    cvt_f16<<<NA4 / 256, 256>>>(key, fA, NA4);
    transpose_f16<<<tw, tb>>>(Wk, fW, HID, HID);
    gemm_f16<<<gg, 256, GSM4>>>(fA, fW, bk, nullptr, fK);
    // V projection -> fp32, then transpose to fp16
    cvt_f16<<<NA4 / 256, 256>>>(value, fA, NA4);
    transpose_f16<<<tw, tb>>>(Wv, fW, HID, HID);
    gemm_f16<<<gg, 256, GSM4>>>(fA, fW, bv, pV, nullptr);
    transpose_f16<<<dim3(HID / 32, MROWS / 32), tb>>>(pV, fVt, HID, MROWS);

    // attention
    attn_scores_mma<<<dim3(S / 128, S / 128, BATCH * NH), 256, GSM4>>>();
    combine_stats<<<(BATCH * NH * S) / 256, 256>>>();
    attn_av_mma<<<dim3(S / 128, BATCH, NH), 256, AVS>>>();

    if (out_size >= 2 * MROWS * HID) {
        mean_attn<<<(BATCH * S * S / 4) / 256, 256>>>(out + (size_t)MROWS * HID);
    }

    // O projection (attended already fp16 in g_fA)
    transpose_f16<<<tw, tb>>>(Wo, fW, HID, HID);
    gemm_f16<<<gg, 256, GSM4>>>(fA, fW, bo, out, nullptr);
}

// round 16
// speedup vs baseline: 1.0825x; 1.0825x over previous
#include <cuda_runtime.h>
#include <cuda_fp16.h>
#include <cstdint>

#define S 2048
#define HID 2048
#define NH 16
#define HD 128
#define BATCH 2
#define MROWS (BATCH*S)   // 4096

typedef unsigned long long ull;

// ---------------- scratch (static device allocations; no cudaMalloc) --------
__device__ float  g_V [(size_t)MROWS*HID];
__device__ __half g_Sh[(size_t)BATCH*NH*S*S];  // raw scaled scores, fp16 (268 MB)
__device__ float  g_m [BATCH*NH*S];
__device__ float  g_li[BATCH*NH*S];
__device__ float  g_pm[(size_t)BATCH*NH*S*16];
__device__ float  g_pl[(size_t)BATCH*NH*S*16];

// per-chain fp16 buffers so the three projection chains are independent
__device__ __half g_fAq[(size_t)MROWS*HID];    // query fp16 -> later attended
__device__ __half g_fAk[(size_t)MROWS*HID];    // key fp16
__device__ __half g_fAv[(size_t)MROWS*HID];    // value fp16
__device__ __half g_fWq[(size_t)HID*HID];
__device__ __half g_fWk[(size_t)HID*HID];
__device__ __half g_fWv[(size_t)HID*HID];
__device__ __half g_fWo[(size_t)HID*HID];
__device__ __half g_fQ [(size_t)MROWS*HID];
__device__ __half g_fK [(size_t)MROWS*HID];
__device__ __half g_fVt[(size_t)HID*MROWS];    // V^T fp16 [HID x MROWS]

// ======================= PTX helpers =========================================
__device__ __forceinline__ uint32_t smem_u32(const void* p){
    uint32_t a;
    asm("{ .reg .u64 t; cvta.to.shared.u64 t, %1; cvt.u32.u64 %0, t; }" : "=r"(a) : "l"(p));
    return a;
}
#define CP16(sm, gp)  asm volatile("cp.async.cg.shared.global [%0], [%1], 16;" :: "r"(sm), "l"(gp) : "memory")
#define CP_COMMIT()   asm volatile("cp.async.commit_group;" ::: "memory")
#define CP_WAIT1()    asm volatile("cp.async.wait_group 1;" ::: "memory")
#define CP_WAIT0()    asm volatile("cp.async.wait_group 0;" ::: "memory")

#define LDSM4(R, A) asm volatile("ldmatrix.sync.aligned.m8n8.x4.shared.b16 {%0,%1,%2,%3}, [%4];" \
    : "=r"((R)[0]), "=r"((R)[1]), "=r"((R)[2]), "=r"((R)[3]) : "r"(A))

#define MMAF16(D, Af, B0, B1) asm volatile( \
    "mma.sync.aligned.m16n8k16.row.col.f32.f16.f16.f32 " \
    "{%0,%1,%2,%3}, {%4,%5,%6,%7}, {%8,%9}, {%0,%1,%2,%3};" \
    : "+f"((D)[0]), "+f"((D)[1]), "+f"((D)[2]), "+f"((D)[3]) \
    : "r"((Af)[0]), "r"((Af)[1]), "r"((Af)[2]), "r"((Af)[3]), \
      "r"(B0), "r"(B1))

__device__ __forceinline__ uint32_t h2u(float a, float b){
    __half2 h = __floats2half2_rn(a, b);
    return *(uint32_t*)&h;
}

// ======================= prep kernels ========================================
__global__ void __launch_bounds__(256) cvt_f16(
    const float* __restrict__ in, __half* __restrict__ out, int n4)
{
    int i = blockIdx.x * 256 + threadIdx.x;
    if (i >= n4) return;
    float4 v = ((const float4*)in)[i];
    uint32_t a = h2u(v.x, v.y), b = h2u(v.z, v.w);
    ((uint2*)out)[i] = make_uint2(a, b);
}

__global__ void __launch_bounds__(256) transpose_f16(
    const float* __restrict__ in, __half* __restrict__ out, int CI, int RI)
{
    __shared__ float ts[32][33];
    int tx = threadIdx.x, ty = threadIdx.y;
    int n0 = blockIdx.x * 32, k0 = blockIdx.y * 32;
#pragma unroll
    for (int j = 0; j < 4; j++)
        ts[ty + j * 8][tx] = in[(size_t)(k0 + ty + j * 8) * CI + n0 + tx];
    __syncthreads();
#pragma unroll
    for (int j = 0; j < 4; j++)
        out[(size_t)(n0 + ty + j * 8) * RI + k0 + tx] = __float2half(ts[tx][ty + j * 8]);
}

// ======================= fp16 HMMA GEMM: C = A@W + bias ======================
#define BK 32
#define NKCH (HID/BK)                 // 64
#define SSTR 40
#define MATB (128*SSTR*2)             // 10240 B
#define STG2 (2*MATB)                 // 20480 B per stage (A+B)
#define GSM2 (2*STG2)                 // 40960 B
#define AVS  (GSM2 + 1024)

__global__ void __launch_bounds__(256) gemm_f16(
    const __half* __restrict__ A, const __half* __restrict__ B,
    const float* __restrict__ bias, float* __restrict__ C,
    __half* __restrict__ Cf)
{
    extern __shared__ __align__(128) char smg[];
    uint32_t sb = smem_u32(smg);
    int tid = threadIdx.x, lane = tid & 31, wid = tid >> 5;
    int brow = blockIdx.y * 128, bcol = blockIdx.x * 128;
    int wm = (wid >> 1) * 32, wn = (wid & 1) * 64;

    int lr = tid >> 2, lc = (tid & 3) * 8;
    const __half* srcA0 = A + (size_t)(brow + lr) * HID + lc;
    const __half* srcA1 = A + (size_t)(brow + lr + 64) * HID + lc;
    const __half* srcB0 = B + (size_t)(bcol + lr) * HID + lc;
    const __half* srcB1 = B + (size_t)(bcol + lr + 64) * HID + lc;
    uint32_t d0 = (uint32_t)(lr * SSTR + lc) * 2;
    uint32_t d1 = (uint32_t)((lr + 64) * SSTR + lc) * 2;

#define LOAD_CHUNK(kk, st) do { \
    uint32_t bb = sb + (uint32_t)(st) * STG2; \
    int k0 = (kk) * BK; \
    CP16(bb + d0, srcA0 + k0); CP16(bb + d1, srcA1 + k0); \
    CP16(bb + MATB + d0, srcB0 + k0); CP16(bb + MATB + d1, srcB1 + k0); \
    CP_COMMIT(); } while (0)

    uint32_t a_off  = (uint32_t)((wm + (lane & 15)) * SSTR + ((lane >> 1) & 8)) * 2;
    uint32_t b4_off = (uint32_t)((wn + (lane & 7) + ((lane >> 4) << 3)) * SSTR + (lane & 8)) * 2;

    float acc[2][8][4];
#pragma unroll
    for (int mt = 0; mt < 2; mt++)
#pragma unroll
        for (int nt = 0; nt < 8; nt++)
#pragma unroll
            for (int j = 0; j < 4; j++) acc[mt][nt][j] = 0.0f;

    LOAD_CHUNK(0, 0);
    LOAD_CHUNK(1, 1);

    for (int k = 0; k < NKCH; k++) {
        if (k < NKCH - 1) { CP_WAIT1(); } else { CP_WAIT0(); }
        __syncthreads();
        uint32_t stb = sb + (uint32_t)(k & 1) * STG2;
#pragma unroll
        for (int kst = 0; kst < 2; kst++) {
            uint32_t kb = (uint32_t)kst * 32;
            uint32_t a[2][4], b4[4][4];
            LDSM4(a[0], stb + a_off + kb);
            LDSM4(a[1], stb + a_off + kb + 16*SSTR*2);
#pragma unroll
            for (int g = 0; g < 4; g++)
                LDSM4(b4[g], stb + MATB + b4_off + kb + g*16*SSTR*2);
#pragma unroll
            for (int mt = 0; mt < 2; mt++)
#pragma unroll
                for (int g = 0; g < 4; g++) {
                    MMAF16(acc[mt][2*g],   a[mt], b4[g][0], b4[g][1]);
                    MMAF16(acc[mt][2*g+1], a[mt], b4[g][2], b4[g][3]);
                }
        }
        __syncthreads();
        if (k + 2 < NKCH) LOAD_CHUNK(k + 2, k & 1);
    }
#undef LOAD_CHUNK

    int gid = lane >> 2, tig = lane & 3;
#pragma unroll
    for (int mt = 0; mt < 2; mt++) {
        int m0 = brow + wm + mt * 16 + gid;
#pragma unroll
        for (int nt = 0; nt < 8; nt++) {
            int n0 = bcol + wn + nt * 8 + tig * 2;
            float2 bb = *(const float2*)(bias + n0);
            float v0 = acc[mt][nt][0] + bb.x, v1 = acc[mt][nt][1] + bb.y;
            float v2 = acc[mt][nt][2] + bb.x, v3 = acc[mt][nt][3] + bb.y;
            if (Cf) {
                *(uint32_t*)(Cf + (size_t)m0 * HID + n0)     = h2u(v0, v1);
                *(uint32_t*)(Cf + (size_t)(m0+8) * HID + n0) = h2u(v2, v3);
            } else {
                *(float2*)(C + (size_t)m0 * HID + n0)     = make_float2(v0, v1);
                *(float2*)(C + (size_t)(m0+8) * HID + n0) = make_float2(v2, v3);
            }
        }
    }
}

// ================ attention scores: S = scale * Q @ K^T (fp16 HMMA) =========
#define SNK (HD/BK)   // 4
__global__ void __launch_bounds__(256) attn_scores_mma()
{
    extern __shared__ __align__(128) char smg[];
    uint32_t sb = smem_u32(smg);
    int tid = threadIdx.x, lane = tid & 31, wid = tid >> 5;
    int kt = blockIdx.x, qt = blockIdx.y, bh = blockIdx.z;
    int b = bh >> 4, h = bh & 15;
    int wm = (wid >> 1) * 32, wn = (wid & 1) * 64;

    int lr = tid >> 2, lc = (tid & 3) * 8;
    const __half* srcA0 = g_fQ + (size_t)(b*S + qt*128 + lr) * HID + h*HD + lc;
    const __half* srcA1 = srcA0 + (size_t)64 * HID;
    const __half* srcB0 = g_fK + (size_t)(b*S + kt*128 + lr) * HID + h*HD + lc;
    const __half* srcB1 = srcB0 + (size_t)64 * HID;
    uint32_t d0 = (uint32_t)(lr * SSTR + lc) * 2;
    uint32_t d1 = (uint32_t)((lr + 64) * SSTR + lc) * 2;

#define LOAD_CHUNK(kk, st) do { \
    uint32_t bb = sb + (uint32_t)(st) * STG2; \
    int k0 = (kk) * BK; \
    CP16(bb + d0, srcA0 + k0); CP16(bb + d1, srcA1 + k0); \
    CP16(bb + MATB + d0, srcB0 + k0); CP16(bb + MATB + d1, srcB1 + k0); \
    CP_COMMIT(); } while (0)

    uint32_t a_off  = (uint32_t)((wm + (lane & 15)) * SSTR + ((lane >> 1) & 8)) * 2;
    uint32_t b4_off = (uint32_t)((wn + (lane & 7) + ((lane >> 4) << 3)) * SSTR + (lane & 8)) * 2;

    float acc[2][8][4];
#pragma unroll
    for (int mt = 0; mt < 2; mt++)
#pragma unroll
        for (int nt = 0; nt < 8; nt++)
#pragma unroll
            for (int j = 0; j < 4; j++) acc[mt][nt][j] = 0.0f;

    LOAD_CHUNK(0, 0);
    LOAD_CHUNK(1, 1);

    for (int k = 0; k < SNK; k++) {
        if (k < SNK - 1) { CP_WAIT1(); } else { CP_WAIT0(); }
        __syncthreads();
        uint32_t stb = sb + (uint32_t)(k & 1) * STG2;
#pragma unroll
        for (int kst = 0; kst < 2; kst++) {
            uint32_t kb = (uint32_t)kst * 32;
            uint32_t a[2][4], b4[4][4];
            LDSM4(a[0], stb + a_off + kb);
            LDSM4(a[1], stb + a_off + kb + 16*SSTR*2);
#pragma unroll
            for (int g = 0; g < 4; g++)
                LDSM4(b4[g], stb + MATB + b4_off + kb + g*16*SSTR*2);
#pragma unroll
            for (int mt = 0; mt < 2; mt++)
#pragma unroll
                for (int g = 0; g < 4; g++) {
                    MMAF16(acc[mt][2*g],   a[mt], b4[g][0], b4[g][1]);
                    MMAF16(acc[mt][2*g+1], a[mt], b4[g][2], b4[g][3]);
                }
        }
        __syncthreads();
        if (k + 2 < SNK) LOAD_CHUNK(k + 2, k & 1);
    }
#undef LOAD_CHUNK

    const float scale = 0.08838834764831843f;   // 1/sqrt(128)
#pragma unroll
    for (int mt = 0; mt < 2; mt++)
#pragma unroll
        for (int nt = 0; nt < 8; nt++)
#pragma unroll
            for (int j = 0; j < 4; j++) acc[mt][nt][j] *= scale;

    int gid = lane >> 2, tig = lane & 3;
    size_t srow0 = (size_t)bh * S + (size_t)qt * 128;
#pragma unroll
    for (int mt = 0; mt < 2; mt++) {
        size_t m0 = srow0 + wm + mt * 16 + gid;
#pragma unroll
        for (int nt = 0; nt < 8; nt++) {
            int n0 = kt * 128 + wn + nt * 8 + tig * 2;
            *(uint32_t*)&g_Sh[m0 * S + n0]       = h2u(acc[mt][nt][0], acc[mt][nt][1]);
            *(uint32_t*)&g_Sh[(m0 + 8) * S + n0] = h2u(acc[mt][nt][2], acc[mt][nt][3]);
        }
    }

    __syncthreads();
    float* sm = (float*)smg;          // [2][128]
    float* sl = sm + 256;             // [2][128]
#pragma unroll
    for (int mt = 0; mt < 2; mt++) {
#pragma unroll
        for (int half = 0; half < 2; half++) {
            float mx = -1e30f;
#pragma unroll
            for (int nt = 0; nt < 8; nt++)
                mx = fmaxf(mx, fmaxf(acc[mt][nt][half*2], acc[mt][nt][half*2+1]));
            mx = fmaxf(mx, __shfl_xor_sync(0xffffffffu, mx, 1));
            mx = fmaxf(mx, __shfl_xor_sync(0xffffffffu, mx, 2));
            float se = 0.0f;
#pragma unroll
            for (int nt = 0; nt < 8; nt++)
                se += __expf(acc[mt][nt][half*2] - mx) + __expf(acc[mt][nt][half*2+1] - mx);
            se += __shfl_xor_sync(0xffffffffu, se, 1);
            se += __shfl_xor_sync(0xffffffffu, se, 2);
            if (tig == 0) {
                int r = wm + mt * 16 + half * 8 + gid;
                sm[(wid & 1) * 128 + r] = mx;
                sl[(wid & 1) * 128 + r] = se;
            }
        }
    }
    __syncthreads();
    if (tid < 128) {
        float m0 = sm[tid], m1 = sm[128 + tid];
        float l0 = sl[tid], l1 = sl[128 + tid];
        float M = fmaxf(m0, m1);
        float L = l0 * __expf(m0 - M) + l1 * __expf(m1 - M);
        size_t q = (size_t)bh * S + (size_t)qt * 128 + tid;
        g_pm[q * 16 + kt] = M;
        g_pl[q * 16 + kt] = L;
    }
}

// ================ combine partial stats -> m, 1/l ============================
__global__ void __launch_bounds__(256) combine_stats()
{
    int r = blockIdx.x * 256 + threadIdx.x;
    float M = -1e30f;
#pragma unroll
    for (int i = 0; i < 16; i++) M = fmaxf(M, g_pm[(size_t)r * 16 + i]);
    float L = 0.0f;
#pragma unroll
    for (int i = 0; i < 16; i++)
        L += g_pl[(size_t)r * 16 + i] * __expf(g_pm[(size_t)r * 16 + i] - M);
    g_m[r]  = M;
    g_li[r] = 1.0f / L;
}

// ================ attn AV: attended = softmax(S) @ V (fp16 HMMA) =============
__global__ void __launch_bounds__(256) attn_av_mma()
{
    extern __shared__ __align__(128) char smg[];
    uint32_t sb = smem_u32(smg);
    float* msh = (float*)(smg + GSM2);         // [128]
    float* lih = msh + 128;                    // [128]
    int tid = threadIdx.x, lane = tid & 31, wid = tid >> 5;
    int qt = blockIdx.x, b = blockIdx.y, h = blockIdx.z;
    int bh = b * NH + h;
    int wm = (wid >> 1) * 32, wn = (wid & 1) * 64;

    if (tid < 128) {
        size_t q = (size_t)bh * S + (size_t)qt * 128 + tid;
        msh[tid] = g_m[q];
        lih[tid] = g_li[q];
    }
    __syncthreads();

    int pr = tid >> 1, pc = (tid & 1) * 16;
    const __half* srcP = g_Sh + ((size_t)bh * S + (size_t)qt * 128 + pr) * S + pc;
    float pm_r = msh[pr], pli_r = lih[pr];
    uint32_t pdst = (uint32_t)(pr * SSTR + pc) * 2;

    int lr = tid >> 2, lc = (tid & 3) * 8;
    const __half* srcV0 = g_fVt + (size_t)(h*HD + lr) * MROWS + b*S + lc;
    const __half* srcV1 = srcV0 + (size_t)64 * MROWS;
    uint32_t d0 = (uint32_t)(lr * SSTR + lc) * 2;
    uint32_t d1 = (uint32_t)((lr + 64) * SSTR + lc) * 2;

#define LOADV(kk, st) do { \
    uint32_t bb = sb + (uint32_t)(st) * STG2; \
    int k0 = (kk) * BK; \
    CP16(bb + MATB + d0, srcV0 + k0); CP16(bb + MATB + d1, srcV1 + k0); \
    CP_COMMIT(); } while (0)

#define CONVP(kk, st) do { \
    uint32_t bb = sb + (uint32_t)(st) * STG2; \
    int k0 = (kk) * BK; \
    _Pragma("unroll") \
    for (int j = 0; j < 2; j++) { \
        uint4 u = *(const uint4*)(srcP + k0 + j * 8); \
        float2 f0 = __half22float2(*(__half2*)&u.x); \
        float2 f1 = __half22float2(*(__half2*)&u.y); \
        float2 f2 = __half22float2(*(__half2*)&u.z); \
        float2 f3 = __half22float2(*(__half2*)&u.w); \
        uint32_t o0 = h2u(__expf(f0.x - pm_r) * pli_r, __expf(f0.y - pm_r) * pli_r); \
        uint32_t o1 = h2u(__expf(f1.x - pm_r) * pli_r, __expf(f1.y - pm_r) * pli_r); \
        uint32_t o2 = h2u(__expf(f2.x - pm_r) * pli_r, __expf(f2.y - pm_r) * pli_r); \
        uint32_t o3 = h2u(__expf(f3.x - pm_r) * pli_r, __expf(f3.y - pm_r) * pli_r); \
        asm volatile("st.shared.v4.b32 [%0], {%1, %2, %3, %4};" \
            :: "r"(bb + pdst + (uint32_t)j * 16), "r"(o0), "r"(o1), "r"(o2), "r"(o3)); \
    } } while (0)

    uint32_t a_off  = (uint32_t)((wm + (lane & 15)) * SSTR + ((lane >> 1) & 8)) * 2;
    uint32_t b4_off = (uint32_t)((wn + (lane & 7) + ((lane >> 4) << 3)) * SSTR + (lane & 8)) * 2;

    float acc[2][8][4];
#pragma unroll
    for (int mt = 0; mt < 2; mt++)
#pragma unroll
        for (int nt = 0; nt < 8; nt++)
#pragma unroll
            for (int j = 0; j < 4; j++) acc[mt][nt][j] = 0.0f;

    LOADV(0, 0);
    LOADV(1, 1);

    for (int k = 0; k < NKCH; k++) {
        if (k < NKCH - 1) { CP_WAIT1(); } else { CP_WAIT0(); }
        CONVP(k, k & 1);
        __syncthreads();
        uint32_t stb = sb + (uint32_t)(k & 1) * STG2;
#pragma unroll
        for (int kst = 0; kst < 2; kst++) {
            uint32_t kb = (uint32_t)kst * 32;
            uint32_t a[2][4], b4[4][4];
            LDSM4(a[0], stb + a_off + kb);
            LDSM4(a[1], stb + a_off + kb + 16*SSTR*2);
#pragma unroll
            for (int g = 0; g < 4; g++)
                LDSM4(b4[g], stb + MATB + b4_off + kb + g*16*SSTR*2);
#pragma unroll
            for (int mt = 0; mt < 2; mt++)
#pragma unroll
                for (int g = 0; g < 4; g++) {
                    MMAF16(acc[mt][2*g],   a[mt], b4[g][0], b4[g][1]);
                    MMAF16(acc[mt][2*g+1], a[mt], b4[g][2], b4[g][3]);
                }
        }
        __syncthreads();
        if (k + 2 < NKCH) LOADV(k + 2, k & 1);
    }
#undef LOADV
#undef CONVP

    int gid = lane >> 2, tig = lane & 3;
#pragma unroll
    for (int mt = 0; mt < 2; mt++) {
        size_t m0 = (size_t)(b * S + qt * 128 + wm + mt * 16 + gid);
#pragma unroll
        for (int nt = 0; nt < 8; nt++) {
            int n0 = h * HD + wn + nt * 8 + tig * 2;
            *(uint32_t*)(g_fAq + m0 * HID + n0) =
                h2u(acc[mt][nt][0], acc[mt][nt][1]);
            *(uint32_t*)(g_fAq + (m0+8) * HID + n0) =
                h2u(acc[mt][nt][2], acc[mt][nt][3]);
        }
    }
}

// ---------------- head-mean of attention weights (fp16 scores -> exp) -------
__global__ void __launch_bounds__(256) mean_attn(float* __restrict__ out2)
{
    int f = blockIdx.x * 256 + threadIdx.x;
    int b  = f >> 20;
    int r  = f & 1048575;
    int q  = r >> 9;
    int k4 = (r & 511) * 4;
    float mm[NH], ll[NH];
#pragma unroll
    for (int h = 0; h < NH; h++) {
        int bh = b * NH + h;
        mm[h] = g_m[bh * S + q];
        ll[h] = g_li[bh * S + q];
    }
    float4 acc = make_float4(0.f, 0.f, 0.f, 0.f);
#pragma unroll
    for (int h = 0; h < NH; h++) {
        size_t base = ((size_t)(b * NH + h) * S + q) * S + k4;
        uint2 u = *(const uint2*)&g_Sh[base];
        float2 f0 = __half22float2(*(__half2*)&u.x);
        float2 f1 = __half22float2(*(__half2*)&u.y);
        acc.x += __expf(f0.x - mm[h]) * ll[h];
        acc.y += __expf(f0.y - mm[h]) * ll[h];
        acc.z += __expf(f1.x - mm[h]) * ll[h];
        acc.w += __expf(f1.y - mm[h]) * ll[h];
    }
    const float inv = 1.0f / 16.0f;
    acc.x *= inv; acc.y *= inv; acc.z *= inv; acc.w *= inv;
    *(float4*)&out2[(size_t)f * 4] = acc;
}

// ---------------- launch (forked-stream graph) --------------------------------
extern "C" void kernel_launch(void* const* d_in, const int* in_sizes, int n_in,
                              void* d_out, int out_size)
{
    const float* query = (const float*)d_in[0];
    const float* key   = (const float*)d_in[1];
    const float* value = (const float*)d_in[2];
    // d_in[3] rewards, d_in[4] mask: mathematically no-ops
    const float* Wq = (const float*)d_in[5];
    const float* bq = (const float*)d_in[6];
    const float* Wk = (const float*)d_in[7];
    const float* bk = (const float*)d_in[8];
    const float* Wv = (const float*)d_in[9];
    const float* bv = (const float*)d_in[10];
    const float* Wo = (const float*)d_in[11];
    const float* bo = (const float*)d_in[12];
    float* out = (float*)d_out;

    float *pV;
    cudaGetSymbolAddress((void**)&pV, g_V);
    __half *fAq, *fAk, *fAv, *fWq, *fWk, *fWv, *fWo, *fQ, *fK, *fVt;
    cudaGetSymbolAddress((void**)&fAq, g_fAq);
    cudaGetSymbolAddress((void**)&fAk, g_fAk);
    cudaGetSymbolAddress((void**)&fAv, g_fAv);
    cudaGetSymbolAddress((void**)&fWq, g_fWq);
    cudaGetSymbolAddress((void**)&fWk, g_fWk);
    cudaGetSymbolAddress((void**)&fWv, g_fWv);
    cudaGetSymbolAddress((void**)&fWo, g_fWo);
    cudaGetSymbolAddress((void**)&fQ, g_fQ);
    cudaGetSymbolAddress((void**)&fK, g_fK);
    cudaGetSymbolAddress((void**)&fVt, g_fVt);

    cudaFuncSetAttribute(gemm_f16,        cudaFuncAttributeMaxDynamicSharedMemorySize, GSM2);
    cudaFuncSetAttribute(attn_scores_mma, cudaFuncAttributeMaxDynamicSharedMemorySize, GSM2);
    cudaFuncSetAttribute(attn_av_mma,     cudaFuncAttributeMaxDynamicSharedMemorySize, AVS);

    // one-time host resources (no device allocations)
    static cudaStream_t s1 = nullptr, s2 = nullptr;
    static cudaEvent_t evRoot, evB, evC, evCmb, evMean;
    if (!s1) {
        cudaStreamCreateWithFlags(&s1, cudaStreamNonBlocking);
        cudaStreamCreateWithFlags(&s2, cudaStreamNonBlocking);
        cudaEventCreateWithFlags(&evRoot, cudaEventDisableTiming);
        cudaEventCreateWithFlags(&evB,    cudaEventDisableTiming);
        cudaEventCreateWithFlags(&evC,    cudaEventDisableTiming);
        cudaEventCreateWithFlags(&evCmb,  cudaEventDisableTiming);
        cudaEventCreateWithFlags(&evMean, cudaEventDisableTiming);
    }

    const int NA4 = MROWS * HID / 4;
    dim3 tw(HID / 32, HID / 32), tb(32, 8);
    dim3 gg(HID / 128, MROWS / 128);   // (16, 32)

    // fork side streams off the capture (legacy) stream
    cudaEventRecord(evRoot, 0);
    cudaStreamWaitEvent(s1, evRoot, 0);
    cudaStreamWaitEvent(s2, evRoot, 0);

    // --- chain Q on default stream ---
    cvt_f16<<<NA4 / 256, 256>>>(query, fAq, NA4);
    transpose_f16<<<tw, tb>>>(Wq, fWq, HID, HID);
    gemm_f16<<<gg, 256, GSM2>>>(fAq, fWq, bq, nullptr, fQ);

    // --- chain K on s1 ---
    cvt_f16<<<NA4 / 256, 256, 0, s1>>>(key, fAk, NA4);
    transpose_f16<<<tw, tb, 0, s1>>>(Wk, fWk, HID, HID);
    gemm_f16<<<gg, 256, GSM2, s1>>>(fAk, fWk, bk, nullptr, fK);
    cudaEventRecord(evB, s1);

    // --- chain V (+ Wo transpose) on s2 ---
    cvt_f16<<<NA4 / 256, 256, 0, s2>>>(value, fAv, NA4);
    transpose_f16<<<tw, tb, 0, s2>>>(Wv, fWv, HID, HID);
    gemm_f16<<<gg, 256, GSM2, s2>>>(fAv, fWv, bv, pV, nullptr);
    transpose_f16<<<dim3(HID / 32, MROWS / 32), tb, 0, s2>>>(pV, fVt, HID, MROWS);
    transpose_f16<<<tw, tb, 0, s2>>>(Wo, fWo, HID, HID);
    cudaEventRecord(evC, s2);

    // --- attention: scores needs Q (this stream) + K (evB) ---
    cudaStreamWaitEvent(0, evB, 0);
    attn_scores_mma<<<dim3(S / 128, S / 128, BATCH * NH), 256, GSM2>>>();
    combine_stats<<<(BATCH * NH * S) / 256, 256>>>();
    cudaEventRecord(evCmb, 0);

    // --- mean on s1, concurrent with attn_av ---
    if (out_size >= 2 * MROWS * HID) {
        cudaStreamWaitEvent(s1, evCmb, 0);
        mean_attn<<<(BATCH * S * S / 4) / 256, 256, 0, s1>>>(out + (size_t)MROWS * HID);
        cudaEventRecord(evMean, s1);
    }

    // --- AV needs V^T (evC); O-projection needs Wo (also evC) ---
    cudaStreamWaitEvent(0, evC, 0);
    attn_av_mma<<<dim3(S / 128, BATCH, NH), 256, AVS>>>();
    gemm_f16<<<gg, 256, GSM2>>>(fAq, fWo, bo, out, nullptr);

    // --- join ---
    if (out_size >= 2 * MROWS * HID) {
        cudaStreamWaitEvent(0, evMean, 0);
    }
}

// round 17
// speedup vs baseline: 1.0922x; 1.0090x over previous
#include <cuda_runtime.h>
#include <cuda_fp16.h>
#include <cstdint>

#define S 2048
#define HID 2048
#define NH 16
#define HD 128
#define BATCH 2
#define MROWS (BATCH*S)   // 4096

typedef unsigned long long ull;

// ---------------- scratch (static device allocations; no cudaMalloc) --------
__device__ float  g_V [(size_t)MROWS*HID];
__device__ __half g_Sh[(size_t)BATCH*NH*S*S];  // raw scaled scores, fp16 (268 MB)
__device__ float  g_m [BATCH*NH*S];
__device__ float  g_li[BATCH*NH*S];
__device__ float  g_pm[(size_t)BATCH*NH*S*16];
__device__ float  g_pl[(size_t)BATCH*NH*S*16];

// per-chain fp16 buffers so the three projection chains are independent
__device__ __half g_fAq[(size_t)MROWS*HID];    // query fp16 -> later attended
__device__ __half g_fAk[(size_t)MROWS*HID];    // key fp16
__device__ __half g_fAv[(size_t)MROWS*HID];    // value fp16
__device__ __half g_fWq[(size_t)HID*HID];
__device__ __half g_fWk[(size_t)HID*HID];
__device__ __half g_fWv[(size_t)HID*HID];
__device__ __half g_fWo[(size_t)HID*HID];
__device__ __half g_fQ [(size_t)MROWS*HID];
__device__ __half g_fK [(size_t)MROWS*HID];
__device__ __half g_fVt[(size_t)HID*MROWS];    // V^T fp16 [HID x MROWS]

// ======================= PTX helpers =========================================
__device__ __forceinline__ uint32_t smem_u32(const void* p){
    uint32_t a;
    asm("{ .reg .u64 t; cvta.to.shared.u64 t, %1; cvt.u32.u64 %0, t; }" : "=r"(a) : "l"(p));
    return a;
}
#define CP16(sm, gp)  asm volatile("cp.async.cg.shared.global [%0], [%1], 16;" :: "r"(sm), "l"(gp) : "memory")
#define CP_COMMIT()   asm volatile("cp.async.commit_group;" ::: "memory")
#define CP_WAIT1()    asm volatile("cp.async.wait_group 1;" ::: "memory")
#define CP_WAIT0()    asm volatile("cp.async.wait_group 0;" ::: "memory")

#define LDSM4(R, A) asm volatile("ldmatrix.sync.aligned.m8n8.x4.shared.b16 {%0,%1,%2,%3}, [%4];" \
    : "=r"((R)[0]), "=r"((R)[1]), "=r"((R)[2]), "=r"((R)[3]) : "r"(A))

#define MMAF16(D, Af, B0, B1) asm volatile( \
    "mma.sync.aligned.m16n8k16.row.col.f32.f16.f16.f32 " \
    "{%0,%1,%2,%3}, {%4,%5,%6,%7}, {%8,%9}, {%0,%1,%2,%3};" \
    : "+f"((D)[0]), "+f"((D)[1]), "+f"((D)[2]), "+f"((D)[3]) \
    : "r"((Af)[0]), "r"((Af)[1]), "r"((Af)[2]), "r"((Af)[3]), \
      "r"(B0), "r"(B1))

__device__ __forceinline__ uint32_t h2u(float a, float b){
    __half2 h = __floats2half2_rn(a, b);
    return *(uint32_t*)&h;
}

// ======================= prep kernels ========================================
__global__ void __launch_bounds__(256) cvt_f16(
    const float* __restrict__ in, __half* __restrict__ out, int n4)
{
    int i = blockIdx.x * 256 + threadIdx.x;
    if (i >= n4) return;
    float4 v = ((const float4*)in)[i];
    uint32_t a = h2u(v.x, v.y), b = h2u(v.z, v.w);
    ((uint2*)out)[i] = make_uint2(a, b);
}

__global__ void __launch_bounds__(256) transpose_f16(
    const float* __restrict__ in, __half* __restrict__ out, int CI, int RI)
{
    __shared__ float ts[32][33];
    int tx = threadIdx.x, ty = threadIdx.y;
    int n0 = blockIdx.x * 32, k0 = blockIdx.y * 32;
#pragma unroll
    for (int j = 0; j < 4; j++)
        ts[ty + j * 8][tx] = in[(size_t)(k0 + ty + j * 8) * CI + n0 + tx];
    __syncthreads();
#pragma unroll
    for (int j = 0; j < 4; j++)
        out[(size_t)(n0 + ty + j * 8) * RI + k0 + tx] = __float2half(ts[tx][ty + j * 8]);
}

// ======================= fp16 HMMA GEMM: C = A@W + bias ======================
#define BK 32
#define NKCH (HID/BK)                 // 64
#define SSTR 40
#define MATB (128*SSTR*2)             // 10240 B
#define STG2 (2*MATB)                 // 20480 B per stage (A+B)
#define GSM2 (2*STG2)                 // 40960 B
#define AVS  (GSM2 + 1024)

__global__ void __launch_bounds__(256) gemm_f16(
    const __half* __restrict__ A, const __half* __restrict__ B,
    const float* __restrict__ bias, float* __restrict__ C,
    __half* __restrict__ Cf, int mrow0)
{
    extern __shared__ __align__(128) char smg[];
    uint32_t sb = smem_u32(smg);
    int tid = threadIdx.x, lane = tid & 31, wid = tid >> 5;
    int brow = mrow0 + blockIdx.y * 128, bcol = blockIdx.x * 128;
    int wm = (wid >> 1) * 32, wn = (wid & 1) * 64;

    int lr = tid >> 2, lc = (tid & 3) * 8;
    const __half* srcA0 = A + (size_t)(brow + lr) * HID + lc;
    const __half* srcA1 = A + (size_t)(brow + lr + 64) * HID + lc;
    const __half* srcB0 = B + (size_t)(bcol + lr) * HID + lc;
    const __half* srcB1 = B + (size_t)(bcol + lr + 64) * HID + lc;
    uint32_t d0 = (uint32_t)(lr * SSTR + lc) * 2;
    uint32_t d1 = (uint32_t)((lr + 64) * SSTR + lc) * 2;

#define LOAD_CHUNK(kk, st) do { \
    uint32_t bb = sb + (uint32_t)(st) * STG2; \
    int k0 = (kk) * BK; \
    CP16(bb + d0, srcA0 + k0); CP16(bb + d1, srcA1 + k0); \
    CP16(bb + MATB + d0, srcB0 + k0); CP16(bb + MATB + d1, srcB1 + k0); \
    CP_COMMIT(); } while (0)

    uint32_t a_off  = (uint32_t)((wm + (lane & 15)) * SSTR + ((lane >> 1) & 8)) * 2;
    uint32_t b4_off = (uint32_t)((wn + (lane & 7) + ((lane >> 4) << 3)) * SSTR + (lane & 8)) * 2;

    float acc[2][8][4];
#pragma unroll
    for (int mt = 0; mt < 2; mt++)
#pragma unroll
        for (int nt = 0; nt < 8; nt++)
#pragma unroll
            for (int j = 0; j < 4; j++) acc[mt][nt][j] = 0.0f;

    LOAD_CHUNK(0, 0);
    LOAD_CHUNK(1, 1);

    for (int k = 0; k < NKCH; k++) {
        if (k < NKCH - 1) { CP_WAIT1(); } else { CP_WAIT0(); }
        __syncthreads();
        uint32_t stb = sb + (uint32_t)(k & 1) * STG2;
#pragma unroll
        for (int kst = 0; kst < 2; kst++) {
            uint32_t kb = (uint32_t)kst * 32;
            uint32_t a[2][4], b4[4][4];
            LDSM4(a[0], stb + a_off + kb);
            LDSM4(a[1], stb + a_off + kb + 16*SSTR*2);
#pragma unroll
            for (int g = 0; g < 4; g++)
                LDSM4(b4[g], stb + MATB + b4_off + kb + g*16*SSTR*2);
#pragma unroll
            for (int mt = 0; mt < 2; mt++)
#pragma unroll
                for (int g = 0; g < 4; g++) {
                    MMAF16(acc[mt][2*g],   a[mt], b4[g][0], b4[g][1]);
                    MMAF16(acc[mt][2*g+1], a[mt], b4[g][2], b4[g][3]);
                }
        }
        __syncthreads();
        if (k + 2 < NKCH) LOAD_CHUNK(k + 2, k & 1);
    }
#undef LOAD_CHUNK

    int gid = lane >> 2, tig = lane & 3;
#pragma unroll
    for (int mt = 0; mt < 2; mt++) {
        int m0 = brow + wm + mt * 16 + gid;
#pragma unroll
        for (int nt = 0; nt < 8; nt++) {
            int n0 = bcol + wn + nt * 8 + tig * 2;
            float2 bb = *(const float2*)(bias + n0);
            float v0 = acc[mt][nt][0] + bb.x, v1 = acc[mt][nt][1] + bb.y;
            float v2 = acc[mt][nt][2] + bb.x, v3 = acc[mt][nt][3] + bb.y;
            if (Cf) {
                *(uint32_t*)(Cf + (size_t)m0 * HID + n0)     = h2u(v0, v1);
                *(uint32_t*)(Cf + (size_t)(m0+8) * HID + n0) = h2u(v2, v3);
            } else {
                *(float2*)(C + (size_t)m0 * HID + n0)     = make_float2(v0, v1);
                *(float2*)(C + (size_t)(m0+8) * HID + n0) = make_float2(v2, v3);
            }
        }
    }
}

// ================ attention scores: S = scale * Q @ K^T (fp16 HMMA) =========
// grid (kt=16, qt=16, h=16); batch passed as arg
#define SNK (HD/BK)   // 4
__global__ void __launch_bounds__(256) attn_scores_mma(int b)
{
    extern __shared__ __align__(128) char smg[];
    uint32_t sb = smem_u32(smg);
    int tid = threadIdx.x, lane = tid & 31, wid = tid >> 5;
    int kt = blockIdx.x, qt = blockIdx.y, h = blockIdx.z;
    int bh = b * NH + h;
    int wm = (wid >> 1) * 32, wn = (wid & 1) * 64;

    int lr = tid >> 2, lc = (tid & 3) * 8;
    const __half* srcA0 = g_fQ + (size_t)(b*S + qt*128 + lr) * HID + h*HD + lc;
    const __half* srcA1 = srcA0 + (size_t)64 * HID;
    const __half* srcB0 = g_fK + (size_t)(b*S + kt*128 + lr) * HID + h*HD + lc;
    const __half* srcB1 = srcB0 + (size_t)64 * HID;
    uint32_t d0 = (uint32_t)(lr * SSTR + lc) * 2;
    uint32_t d1 = (uint32_t)((lr + 64) * SSTR + lc) * 2;

#define LOAD_CHUNK(kk, st) do { \
    uint32_t bb = sb + (uint32_t)(st) * STG2; \
    int k0 = (kk) * BK; \
    CP16(bb + d0, srcA0 + k0); CP16(bb + d1, srcA1 + k0); \
    CP16(bb + MATB + d0, srcB0 + k0); CP16(bb + MATB + d1, srcB1 + k0); \
    CP_COMMIT(); } while (0)

    uint32_t a_off  = (uint32_t)((wm + (lane & 15)) * SSTR + ((lane >> 1) & 8)) * 2;
    uint32_t b4_off = (uint32_t)((wn + (lane & 7) + ((lane >> 4) << 3)) * SSTR + (lane & 8)) * 2;

    float acc[2][8][4];
#pragma unroll
    for (int mt = 0; mt < 2; mt++)
#pragma unroll
        for (int nt = 0; nt < 8; nt++)
#pragma unroll
            for (int j = 0; j < 4; j++) acc[mt][nt][j] = 0.0f;

    LOAD_CHUNK(0, 0);
    LOAD_CHUNK(1, 1);

    for (int k = 0; k < SNK; k++) {
        if (k < SNK - 1) { CP_WAIT1(); } else { CP_WAIT0(); }
        __syncthreads();
        uint32_t stb = sb + (uint32_t)(k & 1) * STG2;
#pragma unroll
        for (int kst = 0; kst < 2; kst++) {
            uint32_t kb = (uint32_t)kst * 32;
            uint32_t a[2][4], b4[4][4];
            LDSM4(a[0], stb + a_off + kb);
            LDSM4(a[1], stb + a_off + kb + 16*SSTR*2);
#pragma unroll
            for (int g = 0; g < 4; g++)
                LDSM4(b4[g], stb + MATB + b4_off + kb + g*16*SSTR*2);
#pragma unroll
            for (int mt = 0; mt < 2; mt++)
#pragma unroll
                for (int g = 0; g < 4; g++) {
                    MMAF16(acc[mt][2*g],   a[mt], b4[g][0], b4[g][1]);
                    MMAF16(acc[mt][2*g+1], a[mt], b4[g][2], b4[g][3]);
                }
        }
        __syncthreads();
        if (k + 2 < SNK) LOAD_CHUNK(k + 2, k & 1);
    }
#undef LOAD_CHUNK

    const float scale = 0.08838834764831843f;   // 1/sqrt(128)
#pragma unroll
    for (int mt = 0; mt < 2; mt++)
#pragma unroll
        for (int nt = 0; nt < 8; nt++)
#pragma unroll
            for (int j = 0; j < 4; j++) acc[mt][nt][j] *= scale;

    int gid = lane >> 2, tig = lane & 3;
    size_t srow0 = (size_t)bh * S + (size_t)qt * 128;
#pragma unroll
    for (int mt = 0; mt < 2; mt++) {
        size_t m0 = srow0 + wm + mt * 16 + gid;
#pragma unroll
        for (int nt = 0; nt < 8; nt++) {
            int n0 = kt * 128 + wn + nt * 8 + tig * 2;
            *(uint32_t*)&g_Sh[m0 * S + n0]       = h2u(acc[mt][nt][0], acc[mt][nt][1]);
            *(uint32_t*)&g_Sh[(m0 + 8) * S + n0] = h2u(acc[mt][nt][2], acc[mt][nt][3]);
        }
    }

    __syncthreads();
    float* sm = (float*)smg;          // [2][128]
    float* sl = sm + 256;             // [2][128]
#pragma unroll
    for (int mt = 0; mt < 2; mt++) {
#pragma unroll
        for (int half = 0; half < 2; half++) {
            float mx = -1e30f;
#pragma unroll
            for (int nt = 0; nt < 8; nt++)
                mx = fmaxf(mx, fmaxf(acc[mt][nt][half*2], acc[mt][nt][half*2+1]));
            mx = fmaxf(mx, __shfl_xor_sync(0xffffffffu, mx, 1));
            mx = fmaxf(mx, __shfl_xor_sync(0xffffffffu, mx, 2));
            float se = 0.0f;
#pragma unroll
            for (int nt = 0; nt < 8; nt++)
                se += __expf(acc[mt][nt][half*2] - mx) + __expf(acc[mt][nt][half*2+1] - mx);
            se += __shfl_xor_sync(0xffffffffu, se, 1);
            se += __shfl_xor_sync(0xffffffffu, se, 2);
            if (tig == 0) {
                int r = wm + mt * 16 + half * 8 + gid;
                sm[(wid & 1) * 128 + r] = mx;
                sl[(wid & 1) * 128 + r] = se;
            }
        }
    }
    __syncthreads();
    if (tid < 128) {
        float m0 = sm[tid], m1 = sm[128 + tid];
        float l0 = sl[tid], l1 = sl[128 + tid];
        float M = fmaxf(m0, m1);
        float L = l0 * __expf(m0 - M) + l1 * __expf(m1 - M);
        size_t q = (size_t)bh * S + (size_t)qt * 128 + tid;
        g_pm[q * 16 + kt] = M;
        g_pl[q * 16 + kt] = L;
    }
}

// ================ combine partial stats -> m, 1/l (row range) ================
__global__ void __launch_bounds__(256) combine_stats(int roff)
{
    int r = roff + blockIdx.x * 256 + threadIdx.x;
    float M = -1e30f;
#pragma unroll
    for (int i = 0; i < 16; i++) M = fmaxf(M, g_pm[(size_t)r * 16 + i]);
    float L = 0.0f;
#pragma unroll
    for (int i = 0; i < 16; i++)
        L += g_pl[(size_t)r * 16 + i] * __expf(g_pm[(size_t)r * 16 + i] - M);
    g_m[r]  = M;
    g_li[r] = 1.0f / L;
}

// ================ attn AV: attended = softmax(S) @ V (fp16 HMMA) =============
// grid (qt=16, h=16); batch passed as arg
__global__ void __launch_bounds__(256) attn_av_mma(int b)
{
    extern __shared__ __align__(128) char smg[];
    uint32_t sb = smem_u32(smg);
    float* msh = (float*)(smg + GSM2);         // [128]
    float* lih = msh + 128;                    // [128]
    int tid = threadIdx.x, lane = tid & 31, wid = tid >> 5;
    int qt = blockIdx.x, h = blockIdx.y;
    int bh = b * NH + h;
    int wm = (wid >> 1) * 32, wn = (wid & 1) * 64;

    if (tid < 128) {
        size_t q = (size_t)bh * S + (size_t)qt * 128 + tid;
        msh[tid] = g_m[q];
        lih[tid] = g_li[q];
    }
    __syncthreads();

    int pr = tid >> 1, pc = (tid & 1) * 16;
    const __half* srcP = g_Sh + ((size_t)bh * S + (size_t)qt * 128 + pr) * S + pc;
    float pm_r = msh[pr], pli_r = lih[pr];
    uint32_t pdst = (uint32_t)(pr * SSTR + pc) * 2;

    int lr = tid >> 2, lc = (tid & 3) * 8;
    const __half* srcV0 = g_fVt + (size_t)(h*HD + lr) * MROWS + b*S + lc;
    const __half* srcV1 = srcV0 + (size_t)64 * MROWS;
    uint32_t d0 = (uint32_t)(lr * SSTR + lc) * 2;
    uint32_t d1 = (uint32_t)((lr + 64) * SSTR + lc) * 2;

#define LOADV(kk, st) do { \
    uint32_t bb = sb + (uint32_t)(st) * STG2; \
    int k0 = (kk) * BK; \
    CP16(bb + MATB + d0, srcV0 + k0); CP16(bb + MATB + d1, srcV1 + k0); \
    CP_COMMIT(); } while (0)

#define CONVP(kk, st) do { \
    uint32_t bb = sb + (uint32_t)(st) * STG2; \
    int k0 = (kk) * BK; \
    _Pragma("unroll") \
    for (int j = 0; j < 2; j++) { \
        uint4 u = *(const uint4*)(srcP + k0 + j * 8); \
        float2 f0 = __half22float2(*(__half2*)&u.x); \
        float2 f1 = __half22float2(*(__half2*)&u.y); \
        float2 f2 = __half22float2(*(__half2*)&u.z); \
        float2 f3 = __half22float2(*(__half2*)&u.w); \
        uint32_t o0 = h2u(__expf(f0.x - pm_r) * pli_r, __expf(f0.y - pm_r) * pli_r); \
        uint32_t o1 = h2u(__expf(f1.x - pm_r) * pli_r, __expf(f1.y - pm_r) * pli_r); \
        uint32_t o2 = h2u(__expf(f2.x - pm_r) * pli_r, __expf(f2.y - pm_r) * pli_r); \
        uint32_t o3 = h2u(__expf(f3.x - pm_r) * pli_r, __expf(f3.y - pm_r) * pli_r); \
        asm volatile("st.shared.v4.b32 [%0], {%1, %2, %3, %4};" \
            :: "r"(bb + pdst + (uint32_t)j * 16), "r"(o0), "r"(o1), "r"(o2), "r"(o3)); \
    } } while (0)

    uint32_t a_off  = (uint32_t)((wm + (lane & 15)) * SSTR + ((lane >> 1) & 8)) * 2;
    uint32_t b4_off = (uint32_t)((wn + (lane & 7) + ((lane >> 4) << 3)) * SSTR + (lane & 8)) * 2;

    float acc[2][8][4];
#pragma unroll
    for (int mt = 0; mt < 2; mt++)
#pragma unroll
        for (int nt = 0; nt < 8; nt++)
#pragma unroll
            for (int j = 0; j < 4; j++) acc[mt][nt][j] = 0.0f;

    LOADV(0, 0);
    LOADV(1, 1);

    for (int k = 0; k < NKCH; k++) {
        if (k < NKCH - 1) { CP_WAIT1(); } else { CP_WAIT0(); }
        CONVP(k, k & 1);
        __syncthreads();
        uint32_t stb = sb + (uint32_t)(k & 1) * STG2;
#pragma unroll
        for (int kst = 0; kst < 2; kst++) {
            uint32_t kb = (uint32_t)kst * 32;
            uint32_t a[2][4], b4[4][4];
            LDSM4(a[0], stb + a_off + kb);
            LDSM4(a[1], stb + a_off + kb + 16*SSTR*2);
#pragma unroll
            for (int g = 0; g < 4; g++)
                LDSM4(b4[g], stb + MATB + b4_off + kb + g*16*SSTR*2);
#pragma unroll
            for (int mt = 0; mt < 2; mt++)
#pragma unroll
                for (int g = 0; g < 4; g++) {
                    MMAF16(acc[mt][2*g],   a[mt], b4[g][0], b4[g][1]);
                    MMAF16(acc[mt][2*g+1], a[mt], b4[g][2], b4[g][3]);
                }
        }
        __syncthreads();
        if (k + 2 < NKCH) LOADV(k + 2, k & 1);
    }
#undef LOADV
#undef CONVP

    int gid = lane >> 2, tig = lane & 3;
#pragma unroll
    for (int mt = 0; mt < 2; mt++) {
        size_t m0 = (size_t)(b * S + qt * 128 + wm + mt * 16 + gid);
#pragma unroll
        for (int nt = 0; nt < 8; nt++) {
            int n0 = h * HD + wn + nt * 8 + tig * 2;
            *(uint32_t*)(g_fAq + m0 * HID + n0) =
                h2u(acc[mt][nt][0], acc[mt][nt][1]);
            *(uint32_t*)(g_fAq + (m0+8) * HID + n0) =
                h2u(acc[mt][nt][2], acc[mt][nt][3]);
        }
    }
}

// ---------------- head-mean of attention weights (per batch) -----------------
__global__ void __launch_bounds__(256) mean_attn(float* __restrict__ out2, int b)
{
    int f = blockIdx.x * 256 + threadIdx.x;   // 0..2^20-1 (within batch)
    int q  = f >> 9;
    int k4 = (f & 511) * 4;
    float mm[NH], ll[NH];
#pragma unroll
    for (int h = 0; h < NH; h++) {
        int bh = b * NH + h;
        mm[h] = g_m[bh * S + q];
        ll[h] = g_li[bh * S + q];
    }
    float4 acc = make_float4(0.f, 0.f, 0.f, 0.f);
#pragma unroll
    for (int h = 0; h < NH; h++) {
        size_t base = ((size_t)(b * NH + h) * S + q) * S + k4;
        uint2 u = *(const uint2*)&g_Sh[base];
        float2 f0 = __half22float2(*(__half2*)&u.x);
        float2 f1 = __half22float2(*(__half2*)&u.y);
        acc.x += __expf(f0.x - mm[h]) * ll[h];
        acc.y += __expf(f0.y - mm[h]) * ll[h];
        acc.z += __expf(f1.x - mm[h]) * ll[h];
        acc.w += __expf(f1.y - mm[h]) * ll[h];
    }
    const float inv = 1.0f / 16.0f;
    acc.x *= inv; acc.y *= inv; acc.z *= inv; acc.w *= inv;
    *(float4*)&out2[(((size_t)b << 20) + f) * 4] = acc;
}

// ---------------- launch (forked-stream, batch-pipelined graph) --------------
extern "C" void kernel_launch(void* const* d_in, const int* in_sizes, int n_in,
                              void* d_out, int out_size)
{
    const float* query = (const float*)d_in[0];
    const float* key   = (const float*)d_in[1];
    const float* value = (const float*)d_in[2];
    // d_in[3] rewards, d_in[4] mask: mathematically no-ops
    const float* Wq = (const float*)d_in[5];
    const float* bq = (const float*)d_in[6];
    const float* Wk = (const float*)d_in[7];
    const float* bk = (const float*)d_in[8];
    const float* Wv = (const float*)d_in[9];
    const float* bv = (const float*)d_in[10];
    const float* Wo = (const float*)d_in[11];
    const float* bo = (const float*)d_in[12];
    float* out = (float*)d_out;

    float *pV;
    cudaGetSymbolAddress((void**)&pV, g_V);
    __half *fAq, *fAk, *fAv, *fWq, *fWk, *fWv, *fWo, *fQ, *fK, *fVt;
    cudaGetSymbolAddress((void**)&fAq, g_fAq);
    cudaGetSymbolAddress((void**)&fAk, g_fAk);
    cudaGetSymbolAddress((void**)&fAv, g_fAv);
    cudaGetSymbolAddress((void**)&fWq, g_fWq);
    cudaGetSymbolAddress((void**)&fWk, g_fWk);
    cudaGetSymbolAddress((void**)&fWv, g_fWv);
    cudaGetSymbolAddress((void**)&fWo, g_fWo);
    cudaGetSymbolAddress((void**)&fQ, g_fQ);
    cudaGetSymbolAddress((void**)&fK, g_fK);
    cudaGetSymbolAddress((void**)&fVt, g_fVt);

    cudaFuncSetAttribute(gemm_f16,        cudaFuncAttributeMaxDynamicSharedMemorySize, GSM2);
    cudaFuncSetAttribute(attn_scores_mma, cudaFuncAttributeMaxDynamicSharedMemorySize, GSM2);
    cudaFuncSetAttribute(attn_av_mma,     cudaFuncAttributeMaxDynamicSharedMemorySize, AVS);

    // one-time host resources (no device allocations)
    static cudaStream_t s1 = nullptr, s2 = nullptr;
    static cudaEvent_t evRoot, evK, evV, evS0, evS1, evAV0, evAV1, evMean;
    if (!s1) {
        cudaStreamCreateWithFlags(&s1, cudaStreamNonBlocking);
        cudaStreamCreateWithFlags(&s2, cudaStreamNonBlocking);
        cudaEventCreateWithFlags(&evRoot, cudaEventDisableTiming);
        cudaEventCreateWithFlags(&evK,    cudaEventDisableTiming);
        cudaEventCreateWithFlags(&evV,    cudaEventDisableTiming);
        cudaEventCreateWithFlags(&evS0,   cudaEventDisableTiming);
        cudaEventCreateWithFlags(&evS1,   cudaEventDisableTiming);
        cudaEventCreateWithFlags(&evAV0,  cudaEventDisableTiming);
        cudaEventCreateWithFlags(&evAV1,  cudaEventDisableTiming);
        cudaEventCreateWithFlags(&evMean, cudaEventDisableTiming);
    }

    const int NA4 = MROWS * HID / 4;
    dim3 tw(HID / 32, HID / 32), tb(32, 8);
    dim3 gg(HID / 128, MROWS / 128);     // (16, 32) full
    dim3 gh(HID / 128, S / 128);         // (16, 16) one batch of rows

    // fork side streams off the capture stream
    cudaEventRecord(evRoot, 0);
    cudaStreamWaitEvent(s1, evRoot, 0);
    cudaStreamWaitEvent(s2, evRoot, 0);

    // --- chain Q on default stream ---
    cvt_f16<<<NA4 / 256, 256>>>(query, fAq, NA4);
    transpose_f16<<<tw, tb>>>(Wq, fWq, HID, HID);
    gemm_f16<<<gg, 256, GSM2>>>(fAq, fWq, bq, nullptr, fQ, 0);

    // --- chain K on s1 ---
    cvt_f16<<<NA4 / 256, 256, 0, s1>>>(key, fAk, NA4);
    transpose_f16<<<tw, tb, 0, s1>>>(Wk, fWk, HID, HID);
    gemm_f16<<<gg, 256, GSM2, s1>>>(fAk, fWk, bk, nullptr, fK, 0);
    cudaEventRecord(evK, s1);

    // --- chain V (+ Wo transpose) on s2 ---
    cvt_f16<<<NA4 / 256, 256, 0, s2>>>(value, fAv, NA4);
    transpose_f16<<<tw, tb, 0, s2>>>(Wv, fWv, HID, HID);
    gemm_f16<<<gg, 256, GSM2, s2>>>(fAv, fWv, bv, pV, nullptr, 0);
    transpose_f16<<<dim3(HID / 32, MROWS / 32), tb, 0, s2>>>(pV, fVt, HID, MROWS);
    transpose_f16<<<tw, tb, 0, s2>>>(Wo, fWo, HID, HID);
    cudaEventRecord(evV, s2);

    const bool wantMean = (out_size >= 2 * MROWS * HID);
    dim3 gsc(S / 128, S / 128, NH);      // per-batch scores grid
    dim3 gav(S / 128, NH);               // per-batch AV grid

    // --- scores/combine per batch on default stream ---
    cudaStreamWaitEvent(0, evK, 0);
    attn_scores_mma<<<gsc, 256, GSM2>>>(0);
    combine_stats<<<(NH * S) / 256, 256>>>(0);
    cudaEventRecord(evS0, 0);
    attn_scores_mma<<<gsc, 256, GSM2>>>(1);
    combine_stats<<<(NH * S) / 256, 256>>>(NH * S);
    cudaEventRecord(evS1, 0);

    // --- AV per batch on s1 (overlaps scores(b1) and gemmO(b0)) ---
    cudaStreamWaitEvent(s1, evV, 0);
    cudaStreamWaitEvent(s1, evS0, 0);
    attn_av_mma<<<gav, 256, AVS, s1>>>(0);
    cudaEventRecord(evAV0, s1);
    cudaStreamWaitEvent(s1, evS1, 0);
    attn_av_mma<<<gav, 256, AVS, s1>>>(1);
    cudaEventRecord(evAV1, s1);

    // --- mean per batch on s2 (pure-bandwidth; overlaps AV/gemmO) ---
    if (wantMean) {
        cudaStreamWaitEvent(s2, evS0, 0);
        mean_attn<<<(S * S / 4) / 256, 256, 0, s2>>>(out + (size_t)MROWS * HID, 0);
        cudaStreamWaitEvent(s2, evS1, 0);
        mean_attn<<<(S * S / 4) / 256, 256, 0, s2>>>(out + (size_t)MROWS * HID, 1);
        cudaEventRecord(evMean, s2);
    }

    // --- O projection per batch on default stream ---
    cudaStreamWaitEvent(0, evAV0, 0);
    gemm_f16<<<gh, 256, GSM2>>>(fAq, fWo, bo, out, nullptr, 0);
    cudaStreamWaitEvent(0, evAV1, 0);
    gemm_f16<<<gh, 256, GSM2>>>(fAq, fWo, bo, out, nullptr, S);

    // --- join ---
    if (wantMean) {
        cudaStreamWaitEvent(0, evMean, 0);
    }
}